// round 1
// baseline (speedup 1.0000x reference)
#include <cuda_runtime.h>
#include <math.h>

// Problem constants
#define O_DIM 32
#define I_DIM 32
#define K_DIM 13
#define N_DIM 4096
#define IK    (I_DIM * K_DIM)    // 416
#define WSIZE (O_DIM * IK)       // 13312 floats = 53248 B

#define THREADS 1024
#define BLOCKS  304              // 152 SMs * 2 resident blocks

__global__ void __launch_bounds__(THREADS, 2) plaq_kernel(
    const float* __restrict__ x,       // (I, N)
    const float* __restrict__ W,       // (O, I, K)
    const float* __restrict__ b,       // (O,)
    const float* __restrict__ mask,    // (N, O, I, K)
    const int*   __restrict__ shifts,  // (N, K)
    float*       __restrict__ out)     // (O, N)
{
    __shared__ float Wsh[WSIZE];
    __shared__ float gsh[IK];

    const int tid  = threadIdx.x;
    const int warp = tid >> 5;   // warp == o
    const int lane = tid & 31;

    // Load W once per (persistent) block: 13312 floats / 1024 threads = 13 each
    #pragma unroll
    for (int e = tid; e < WSIZE; e += THREADS)
        Wsh[e] = W[e];
    __syncthreads();

    const float bias = b[warp];
    const float e_const = 2.718281828459045f;
    const float scale = (2.0f + 2.0f * e_const) / (e_const - 1.0f);

    for (int n = blockIdx.x; n < N_DIM; n += gridDim.x) {
        // Gather g[i,k] = x[i, shifts[n,k]] (416 scattered L2-hit loads)
        if (tid < IK) {
            const int i = tid / K_DIM;
            const int k = tid - i * K_DIM;
            const int s = shifts[n * K_DIM + k];
            gsh[tid] = x[i * N_DIM + s];
        }
        __syncthreads();

        // Each warp owns one o: 416 contiguous mask floats = 13 coalesced 128B loads
        const float* __restrict__ mrow = mask + ((size_t)n * O_DIM + warp) * IK;
        const float* __restrict__ wrow = Wsh + warp * IK;

        float sum = 0.0f;
        #pragma unroll
        for (int j = 0; j < K_DIM; ++j) {
            const int e = j * 32 + lane;     // 13*32 == 416 exactly
            sum += mrow[e] * wrow[e] * gsh[e];
        }

        // Warp reduction
        #pragma unroll
        for (int off = 16; off > 0; off >>= 1)
            sum += __shfl_xor_sync(0xffffffffu, sum, off);

        if (lane == 0) {
            const float y   = sum + bias;
            const float sig = 1.0f / (1.0f + expf(-y));
            out[warp * N_DIM + n] = (sig - 0.5f) * scale;
        }
        __syncthreads();   // protect gsh before next iteration overwrites it
    }
}

extern "C" void kernel_launch(void* const* d_in, const int* in_sizes, int n_in,
                              void* d_out, int out_size) {
    const float* x      = (const float*)d_in[0];
    const float* Wconv  = (const float*)d_in[1];
    const float* bconv  = (const float*)d_in[2];
    const float* mask   = (const float*)d_in[3];
    const int*   shifts = (const int*)d_in[4];
    float* out          = (float*)d_out;

    plaq_kernel<<<BLOCKS, THREADS>>>(x, Wconv, bconv, mask, shifts, out);
}